// round 1
// baseline (speedup 1.0000x reference)
#include <cuda_runtime.h>
#include <math.h>

// Problem constants (shapes fixed by the reference: features [262144,256], 1000 classes)
#define NUM_C 1000
#define DIMS  256
#define NMAX  262144
#define TILES 16   // ceil(1000/64)

// ---- device scratch (no allocations allowed) ----
__device__ int   g_counts[NUM_C];
__device__ int   g_offsets[NUM_C];
__device__ int   g_cursor[NUM_C];
__device__ int   g_idx[NMAX];
__device__ float g_mn[NUM_C * DIMS];   // L2-normalized class means
__device__ int   g_maxkey;             // float-as-int key of (max_dot + 4.0f), monotone for positive floats

// ---------------------------------------------------------------------------
__global__ void init_k() {
    int i = blockIdx.x * blockDim.x + threadIdx.x;
    if (i < NUM_C) g_counts[i] = 0;
    if (i == 0)    g_maxkey = 0;   // encodes dot = -4.0, below any real candidate
}

// Per-CTA shared histogram, then flush to global.
__global__ void hist_k(const int* __restrict__ labels, int n) {
    __shared__ int h[NUM_C];
    for (int i = threadIdx.x; i < NUM_C; i += blockDim.x) h[i] = 0;
    __syncthreads();
    for (int i = blockIdx.x * blockDim.x + threadIdx.x; i < n; i += gridDim.x * blockDim.x)
        atomicAdd(&h[labels[i]], 1);
    __syncthreads();
    for (int i = threadIdx.x; i < NUM_C; i += blockDim.x) {
        int v = h[i];
        if (v) atomicAdd(&g_counts[i], v);
    }
}

// Single-CTA Hillis-Steele exclusive scan over the 1000 counts.
__global__ void scan_k() {
    __shared__ int s[1024];
    int t = threadIdx.x;
    int v = (t < NUM_C) ? g_counts[t] : 0;
    s[t] = v;
    __syncthreads();
    for (int off = 1; off < 1024; off <<= 1) {
        int u = (t >= off) ? s[t - off] : 0;
        __syncthreads();
        s[t] += u;
        __syncthreads();
    }
    if (t < NUM_C) {
        int excl = s[t] - v;
        g_offsets[t] = excl;
        g_cursor[t]  = excl;
    }
}

// Scatter row indices into class-contiguous order (order within class irrelevant).
__global__ void scatter_k(const int* __restrict__ labels, int n) {
    for (int i = blockIdx.x * blockDim.x + threadIdx.x; i < n; i += gridDim.x * blockDim.x) {
        int lab = labels[i];
        int pos = atomicAdd(&g_cursor[lab], 1);
        g_idx[pos] = i;
    }
}

// One CTA per class: thread t owns column t. Fully coalesced 1KB-row gathers,
// register accumulation, no atomics. Then normalize the mean in-block.
__global__ void gather_k(const float* __restrict__ f) {
    int c = blockIdx.x;
    int t = threadIdx.x;
    int beg = g_offsets[c];
    int cnt = g_counts[c];
    __shared__ int sidx[256];
    float acc = 0.f;
    for (int base = 0; base < cnt; base += 256) {
        int m = cnt - base; if (m > 256) m = 256;
        __syncthreads();
        if (t < m) sidx[t] = g_idx[beg + base + t];
        __syncthreads();
        int k = 0;
        for (; k + 4 <= m; k += 4) {
            int r0 = sidx[k], r1 = sidx[k+1], r2 = sidx[k+2], r3 = sidx[k+3];
            float v0 = f[r0 * DIMS + t];
            float v1 = f[r1 * DIMS + t];
            float v2 = f[r2 * DIMS + t];
            float v3 = f[r3 * DIMS + t];
            acc += v0; acc += v1; acc += v2; acc += v3;
        }
        for (; k < m; k++) acc += f[sidx[k] * DIMS + t];
    }
    float denom = (cnt > 0) ? (float)cnt : 1.0f;
    float mean = acc / denom;

    // block-reduce sum of squares
    float ss = mean * mean;
    #pragma unroll
    for (int o = 16; o > 0; o >>= 1) ss += __shfl_xor_sync(0xffffffffu, ss, o);
    __shared__ float wsum[8];
    __shared__ float sinv;
    if ((t & 31) == 0) wsum[t >> 5] = ss;
    __syncthreads();
    if (t == 0) {
        float tot = 0.f;
        #pragma unroll
        for (int w = 0; w < 8; w++) tot += wsum[w];
        sinv = (tot > 0.f) ? rsqrtf(tot) : 0.f;
    }
    __syncthreads();
    g_mn[c * DIMS + t] = mean * sinv;
}

// Upper-triangular tiled "GEMM" that reduces straight to a max over off-diagonal
// dot products. 64x64 tiles, 4x4 microtiles, K=256 staged transposed in smem.
__global__ void gemmmax_k() {
    extern __shared__ float sm[];
    float* As = sm;                 // [256][68] : As[k*68 + i]
    float* Bs = sm + 256 * 68;      // [256][68]

    // decode blockIdx -> (ti, tj) with ti <= tj
    int b = blockIdx.x;
    int ti = 0, rl = TILES;
    while (b >= rl) { b -= rl; ti++; rl--; }
    int tj = ti + b;

    int t = threadIdx.x;            // 256 threads; t == k during loads
    for (int it = 0; it < 64; ++it) {
        int rowA = ti * 64 + it;
        int rowB = tj * 64 + it;
        As[t * 68 + it] = (rowA < NUM_C) ? g_mn[rowA * DIMS + t] : 0.f;
        Bs[t * 68 + it] = (rowB < NUM_C) ? g_mn[rowB * DIMS + t] : 0.f;
    }
    __syncthreads();

    int tx = t & 15, ty = t >> 4;
    float cc[4][4];
    #pragma unroll
    for (int i = 0; i < 4; i++)
        #pragma unroll
        for (int j = 0; j < 4; j++) cc[i][j] = 0.f;

    #pragma unroll 4
    for (int k = 0; k < 256; k++) {
        float4 a4 = *(const float4*)(As + k * 68 + tx * 4);
        float4 b4 = *(const float4*)(Bs + k * 68 + ty * 4);
        float av[4] = {a4.x, a4.y, a4.z, a4.w};
        float bv[4] = {b4.x, b4.y, b4.z, b4.w};
        #pragma unroll
        for (int i = 0; i < 4; i++)
            #pragma unroll
            for (int j = 0; j < 4; j++) cc[i][j] += av[i] * bv[j];
    }

    // only count strict upper triangle (gi < gj) and valid rows
    float lm = -4.0f;
    #pragma unroll
    for (int i = 0; i < 4; i++) {
        int gi = ti * 64 + tx * 4 + i;
        #pragma unroll
        for (int j = 0; j < 4; j++) {
            int gj = tj * 64 + ty * 4 + j;
            if (gi < gj && gj < NUM_C) lm = fmaxf(lm, cc[i][j]);
        }
    }
    #pragma unroll
    for (int o = 16; o > 0; o >>= 1) lm = fmaxf(lm, __shfl_xor_sync(0xffffffffu, lm, o));
    __shared__ float wm[8];
    if ((t & 31) == 0) wm[t >> 5] = lm;
    __syncthreads();
    if (t == 0) {
        float m = wm[0];
        #pragma unroll
        for (int w = 1; w < 8; w++) m = fmaxf(m, wm[w]);
        atomicMax(&g_maxkey, __float_as_int(m + 4.0f));  // positive floats: int max == float max
    }
}

__global__ void final_k(float* out, int n) {
    float maxd = __int_as_float(g_maxkey) - 4.0f;
    maxd = fminf(fmaxf(maxd, -1.f), 1.f);     // clip
    float mind = 1.0f - maxd;                 // min off-diagonal cosine distance
    float loss = logf(1.0f / (mind + 1e-6f) + 1.0f);
    for (int i = 0; i < n; i++) out[i] = loss;
}

// ---------------------------------------------------------------------------
extern "C" void kernel_launch(void* const* d_in, const int* in_sizes, int n_in,
                              void* d_out, int out_size) {
    const float* features = (const float*)d_in[0];
    const int*   labels   = (const int*)d_in[1];
    // d_in[2] (conf_mat) is dead in the reference computation.
    int n = in_sizes[1];

    const int smem_gemm = 2 * 256 * 68 * (int)sizeof(float); // 139264 B
    cudaFuncSetAttribute(gemmmax_k, cudaFuncAttributeMaxDynamicSharedMemorySize, smem_gemm);

    init_k<<<4, 256>>>();
    hist_k<<<148, 512>>>(labels, n);
    scan_k<<<1, 1024>>>();
    scatter_k<<<512, 256>>>(labels, n);
    gather_k<<<NUM_C, 256>>>(features);
    gemmmax_k<<<TILES * (TILES + 1) / 2, 256, smem_gemm>>>();
    final_k<<<1, 1>>>((float*)d_out, out_size);
}